// round 1
// baseline (speedup 1.0000x reference)
#include <cuda_runtime.h>
#include <cstdint>
#include <math.h>

// Problem dims
#define T_TOK 2048   // B*S tokens
#define DM    2048   // d_model
#define FM    8192   // d_ff
#define EM    4      // experts
#define KM    2      // top-k

// GEMM tiling
#define BM 128
#define BN 64
#define BK 32
#define NTHREADS 256

// ---------------- scratch (static device allocations are the allowed path) ----
__device__ int   g_count[EM];
__device__ int   g_bucket[EM * T_TOK];          // token id per (expert, slot)
__device__ float g_gate[EM * T_TOK];            // gate prob per (expert, slot)
__device__ int   g_slot[T_TOK * KM];            // global slot id (e*T+pos) per (token,k)
__device__ float g_H[(size_t)EM * T_TOK * FM];  // SwiGLU hidden, 256MB
__device__ float g_Y[(size_t)EM * T_TOK * DM];  // per-slot down-proj output, 64MB

// ---------------- helpers ----------------------------------------------------
__device__ __forceinline__ uint32_t f2tf(float f) {
    uint32_t r;
    asm("cvt.rna.tf32.f32 %0, %1;" : "=r"(r) : "f"(f));
    return r;
}

__device__ __forceinline__ void mma_tf32(float* c, const uint32_t* a, const uint32_t* b) {
    asm volatile(
        "mma.sync.aligned.m16n8k8.row.col.f32.tf32.tf32.f32 "
        "{%0,%1,%2,%3}, {%4,%5,%6,%7}, {%8,%9}, {%0,%1,%2,%3};\n"
        : "+f"(c[0]), "+f"(c[1]), "+f"(c[2]), "+f"(c[3])
        : "r"(a[0]), "r"(a[1]), "r"(a[2]), "r"(a[3]), "r"(b[0]), "r"(b[1]));
}

__device__ __forceinline__ float silu_f(float x) {
    return x / (1.0f + expf(-x));
}

// ---------------- kernels ----------------------------------------------------
__global__ void init_counts_kernel() {
    if (threadIdx.x < EM) g_count[threadIdx.x] = 0;
}

// One block per token: logits = x[t] @ Wr, softmax, top-2, bucket append.
__global__ void router_kernel(const float* __restrict__ x, const float* __restrict__ Wr) {
    const int t = blockIdx.x;
    const int tid = threadIdx.x;
    const float* xr = x + (size_t)t * DM;

    float acc[EM] = {0.f, 0.f, 0.f, 0.f};
    for (int d = tid; d < DM; d += 128) {
        const float xv = xr[d];
#pragma unroll
        for (int e = 0; e < EM; e++) acc[e] += xv * Wr[d * EM + e];
    }

    __shared__ float sred[EM][128];
#pragma unroll
    for (int e = 0; e < EM; e++) sred[e][tid] = acc[e];
    __syncthreads();
    for (int s = 64; s > 0; s >>= 1) {
        if (tid < s) {
#pragma unroll
            for (int e = 0; e < EM; e++) sred[e][tid] += sred[e][tid + s];
        }
        __syncthreads();
    }

    if (tid == 0) {
        float l[EM];
#pragma unroll
        for (int e = 0; e < EM; e++) l[e] = sred[e][0];
        float mx = l[0];
#pragma unroll
        for (int e = 1; e < EM; e++) mx = fmaxf(mx, l[e]);
        float p[EM], sum = 0.f;
#pragma unroll
        for (int e = 0; e < EM; e++) { p[e] = expf(l[e] - mx); sum += p[e]; }
        const float inv = 1.0f / sum;
#pragma unroll
        for (int e = 0; e < EM; e++) p[e] *= inv;

        // top-2, ties -> lower index (matches jax top_k)
        int e0 = 0;
#pragma unroll
        for (int e = 1; e < EM; e++) if (p[e] > p[e0]) e0 = e;
        int e1 = -1;
#pragma unroll
        for (int e = 0; e < EM; e++) {
            if (e == e0) continue;
            if (e1 < 0 || p[e] > p[e1]) e1 = e;
        }

        int s0 = atomicAdd(&g_count[e0], 1);
        g_bucket[e0 * T_TOK + s0] = t;
        g_gate[e0 * T_TOK + s0]   = p[e0];
        g_slot[t * KM + 0]        = e0 * T_TOK + s0;

        int s1 = atomicAdd(&g_count[e1], 1);
        g_bucket[e1 * T_TOK + s1] = t;
        g_gate[e1 * T_TOK + s1]   = p[e1];
        g_slot[t * KM + 1]        = e1 * T_TOK + s1;
    }
}

// Grouped GEMM1: for expert e, H[slot, f] = silu(x Wg) * (x Wu).
// grid = (m_tiles=16, f_tiles=128, experts=4), block = 256 threads.
__global__ __launch_bounds__(NTHREADS)
void gemm1_kernel(const float* __restrict__ x,
                  const float* __restrict__ Wg,
                  const float* __restrict__ Wu) {
    const int e  = blockIdx.z;
    const int cnt = g_count[e];
    const int m0 = blockIdx.x * BM;
    if (m0 >= cnt) return;
    const int f0 = blockIdx.y * BN;

    const int tid  = threadIdx.x;
    const int warp = tid >> 5;
    const int lane = tid & 31;
    const int wm = warp & 3;        // 4 warps along M (32 rows each)
    const int wn = warp >> 2;       // 2 warps along N (32 cols each)
    const int q  = lane >> 2;       // 0..7
    const int r2 = lane & 3;        // 0..3

    __shared__ __align__(16) uint32_t As[BM][36];
    __shared__ __align__(16) uint32_t Bg[BK][72];
    __shared__ __align__(16) uint32_t Bu[BK][72];
    __shared__ int rows[BM];

    if (tid < BM) {
        const int m = m0 + tid;
        rows[tid] = (m < cnt) ? g_bucket[e * T_TOK + m] : -1;
    }

    const float* Wge = Wg + (size_t)e * DM * FM;
    const float* Wue = Wu + (size_t)e * DM * FM;

    float accG[2][4][4];
    float accU[2][4][4];
#pragma unroll
    for (int mi = 0; mi < 2; mi++)
#pragma unroll
        for (int ni = 0; ni < 4; ni++)
#pragma unroll
            for (int j = 0; j < 4; j++) { accG[mi][ni][j] = 0.f; accU[mi][ni][j] = 0.f; }

    __syncthreads();

    for (int kt = 0; kt < DM / BK; kt++) {
        const int k0 = kt * BK;
        // A tile: 128 x 32 floats, gathered rows, tf32-converted
#pragma unroll
        for (int p = 0; p < 4; p++) {
            const int idx = tid + p * NTHREADS;
            const int rr = idx >> 3;
            const int c4 = idx & 7;
            const int tok = rows[rr];
            float4 v = make_float4(0.f, 0.f, 0.f, 0.f);
            if (tok >= 0)
                v = *(const float4*)(x + (size_t)tok * DM + k0 + c4 * 4);
            uint4 w = make_uint4(f2tf(v.x), f2tf(v.y), f2tf(v.z), f2tf(v.w));
            *(uint4*)&As[rr][c4 * 4] = w;
        }
        // B tiles: 32 x 64 each for Wg and Wu
#pragma unroll
        for (int p = 0; p < 2; p++) {
            const int idx = tid + p * NTHREADS;
            const int kr = idx >> 4;
            const int c4 = idx & 15;
            const size_t goff = (size_t)(k0 + kr) * FM + f0 + c4 * 4;
            float4 vg = *(const float4*)(Wge + goff);
            float4 vu = *(const float4*)(Wue + goff);
            *(uint4*)&Bg[kr][c4 * 4] = make_uint4(f2tf(vg.x), f2tf(vg.y), f2tf(vg.z), f2tf(vg.w));
            *(uint4*)&Bu[kr][c4 * 4] = make_uint4(f2tf(vu.x), f2tf(vu.y), f2tf(vu.z), f2tf(vu.w));
        }
        __syncthreads();

#pragma unroll
        for (int k8 = 0; k8 < 4; k8++) {
            const int kk = k8 * 8;
            uint32_t a[2][4];
#pragma unroll
            for (int mi = 0; mi < 2; mi++) {
                const int mr = wm * 32 + mi * 16 + q;
                a[mi][0] = As[mr][kk + r2];
                a[mi][1] = As[mr + 8][kk + r2];
                a[mi][2] = As[mr][kk + r2 + 4];
                a[mi][3] = As[mr + 8][kk + r2 + 4];
            }
#pragma unroll
            for (int ni = 0; ni < 4; ni++) {
                const int nc = wn * 32 + ni * 8 + q;
                uint32_t bg[2] = { Bg[kk + r2][nc], Bg[kk + r2 + 4][nc] };
                uint32_t bu[2] = { Bu[kk + r2][nc], Bu[kk + r2 + 4][nc] };
#pragma unroll
                for (int mi = 0; mi < 2; mi++) {
                    mma_tf32(accG[mi][ni], a[mi], bg);
                    mma_tf32(accU[mi][ni], a[mi], bu);
                }
            }
        }
        __syncthreads();
    }

    // Epilogue: H = silu(g)*u   (padded rows computed from zero A -> write 0, harmless)
#pragma unroll
    for (int mi = 0; mi < 2; mi++) {
#pragma unroll
        for (int ni = 0; ni < 4; ni++) {
            const int mloc = wm * 32 + mi * 16 + q;
            const int col  = f0 + wn * 32 + ni * 8 + r2 * 2;
            const int row0 = m0 + mloc;
            const int row1 = row0 + 8;
            float* h0 = g_H + ((size_t)(e * T_TOK) + row0) * FM + col;
            float* h1 = g_H + ((size_t)(e * T_TOK) + row1) * FM + col;
            h0[0] = silu_f(accG[mi][ni][0]) * accU[mi][ni][0];
            h0[1] = silu_f(accG[mi][ni][1]) * accU[mi][ni][1];
            h1[0] = silu_f(accG[mi][ni][2]) * accU[mi][ni][2];
            h1[1] = silu_f(accG[mi][ni][3]) * accU[mi][ni][3];
        }
    }
}

// Grouped GEMM2: Y[slot, d] = H[slot, :] @ Wd[e].
// grid = (m_tiles=16, d_tiles=32, experts=4), block = 256 threads.
__global__ __launch_bounds__(NTHREADS)
void gemm2_kernel(const float* __restrict__ Wd) {
    const int e  = blockIdx.z;
    const int cnt = g_count[e];
    const int m0 = blockIdx.x * BM;
    if (m0 >= cnt) return;
    const int d0 = blockIdx.y * BN;

    const int tid  = threadIdx.x;
    const int warp = tid >> 5;
    const int lane = tid & 31;
    const int wm = warp & 3;
    const int wn = warp >> 2;
    const int q  = lane >> 2;
    const int r2 = lane & 3;

    __shared__ __align__(16) uint32_t As[BM][36];
    __shared__ __align__(16) uint32_t Bs[BK][72];

    const float* Wde = Wd + (size_t)e * FM * DM;
    const float* Hbase = g_H + (size_t)(e * T_TOK + m0) * FM;

    float acc[2][4][4];
#pragma unroll
    for (int mi = 0; mi < 2; mi++)
#pragma unroll
        for (int ni = 0; ni < 4; ni++)
#pragma unroll
            for (int j = 0; j < 4; j++) acc[mi][ni][j] = 0.f;

    for (int kt = 0; kt < FM / BK; kt++) {
        const int k0 = kt * BK;
#pragma unroll
        for (int p = 0; p < 4; p++) {
            const int idx = tid + p * NTHREADS;
            const int rr = idx >> 3;
            const int c4 = idx & 7;
            float4 v = *(const float4*)(Hbase + (size_t)rr * FM + k0 + c4 * 4);
            *(uint4*)&As[rr][c4 * 4] = make_uint4(f2tf(v.x), f2tf(v.y), f2tf(v.z), f2tf(v.w));
        }
#pragma unroll
        for (int p = 0; p < 2; p++) {
            const int idx = tid + p * NTHREADS;
            const int kr = idx >> 4;
            const int c4 = idx & 15;
            float4 v = *(const float4*)(Wde + (size_t)(k0 + kr) * DM + d0 + c4 * 4);
            *(uint4*)&Bs[kr][c4 * 4] = make_uint4(f2tf(v.x), f2tf(v.y), f2tf(v.z), f2tf(v.w));
        }
        __syncthreads();

#pragma unroll
        for (int k8 = 0; k8 < 4; k8++) {
            const int kk = k8 * 8;
            uint32_t a[2][4];
#pragma unroll
            for (int mi = 0; mi < 2; mi++) {
                const int mr = wm * 32 + mi * 16 + q;
                a[mi][0] = As[mr][kk + r2];
                a[mi][1] = As[mr + 8][kk + r2];
                a[mi][2] = As[mr][kk + r2 + 4];
                a[mi][3] = As[mr + 8][kk + r2 + 4];
            }
#pragma unroll
            for (int ni = 0; ni < 4; ni++) {
                const int nc = wn * 32 + ni * 8 + q;
                uint32_t b[2] = { Bs[kk + r2][nc], Bs[kk + r2 + 4][nc] };
#pragma unroll
                for (int mi = 0; mi < 2; mi++) {
                    mma_tf32(acc[mi][ni], a[mi], b);
                }
            }
        }
        __syncthreads();
    }

#pragma unroll
    for (int mi = 0; mi < 2; mi++) {
#pragma unroll
        for (int ni = 0; ni < 4; ni++) {
            const int mloc = wm * 32 + mi * 16 + q;
            const int col  = d0 + wn * 32 + ni * 8 + r2 * 2;
            const int row0 = m0 + mloc;
            const int row1 = row0 + 8;
            float* y0 = g_Y + ((size_t)(e * T_TOK) + row0) * DM + col;
            float* y1 = g_Y + ((size_t)(e * T_TOK) + row1) * DM + col;
            y0[0] = acc[mi][ni][0];
            y0[1] = acc[mi][ni][1];
            y1[0] = acc[mi][ni][2];
            y1[1] = acc[mi][ni][3];
        }
    }
}

// out[t, :] = gate0 * Y[slot0, :] + gate1 * Y[slot1, :]
__global__ void combine_kernel(float* __restrict__ out) {
    const int i = blockIdx.x * blockDim.x + threadIdx.x;   // over T*DM/4 float4s
    const int t = i / (DM / 4);
    const int c = i % (DM / 4);
    const int s0 = g_slot[t * KM + 0];
    const int s1 = g_slot[t * KM + 1];
    const float w0 = g_gate[s0];
    const float w1 = g_gate[s1];
    const float4 y0 = *((const float4*)g_Y + (size_t)s0 * (DM / 4) + c);
    const float4 y1 = *((const float4*)g_Y + (size_t)s1 * (DM / 4) + c);
    float4 o;
    o.x = w0 * y0.x + w1 * y1.x;
    o.y = w0 * y0.y + w1 * y1.y;
    o.z = w0 * y0.z + w1 * y1.z;
    o.w = w0 * y0.w + w1 * y1.w;
    *((float4*)out + i) = o;
}

// ---------------- launch ------------------------------------------------------
extern "C" void kernel_launch(void* const* d_in, const int* in_sizes, int n_in,
                              void* d_out, int out_size) {
    const float* x  = (const float*)d_in[0];
    const float* Wr = (const float*)d_in[1];
    const float* Wg = (const float*)d_in[2];
    const float* Wu = (const float*)d_in[3];
    const float* Wd = (const float*)d_in[4];
    float* out = (float*)d_out;

    init_counts_kernel<<<1, 32>>>();
    router_kernel<<<T_TOK, 128>>>(x, Wr);
    gemm1_kernel<<<dim3(T_TOK / BM, FM / BN, EM), NTHREADS>>>(x, Wg, Wu);
    gemm2_kernel<<<dim3(T_TOK / BM, DM / BN, EM), NTHREADS>>>(Wd);
    combine_kernel<<<(T_TOK * DM / 4) / NTHREADS, NTHREADS>>>(out);
}

// round 2
// speedup vs baseline: 1.0019x; 1.0019x over previous
#include <cuda_runtime.h>
#include <cstdint>
#include <math.h>

// Problem dims
#define T_TOK 2048   // B*S tokens
#define DM    2048   // d_model
#define FM    8192   // d_ff
#define EM    4      // experts
#define KM    2      // top-k

// GEMM tiling
#define BM 128
#define BN 64
#define BK 32
#define NTHREADS 256

// ---------------- scratch (static device allocations are the allowed path) ----
__device__ int   g_count[EM];
__device__ int   g_bucket[EM * T_TOK];          // token id per (expert, slot)
__device__ float g_gate[EM * T_TOK];            // gate prob per (expert, slot)
__device__ int   g_slot[T_TOK * KM];            // global slot id (e*T+pos) per (token,k)
__device__ float g_H[(size_t)EM * T_TOK * FM];  // SwiGLU hidden, 256MB
__device__ float g_Y[(size_t)EM * T_TOK * DM];  // per-slot down-proj output, 64MB

// ---------------- helpers ----------------------------------------------------
__device__ __forceinline__ uint32_t f2tf(float f) {
    uint32_t r;
    asm("cvt.rna.tf32.f32 %0, %1;" : "=r"(r) : "f"(f));
    return r;
}

__device__ __forceinline__ void mma_tf32(float* c, const uint32_t* a, const uint32_t* b) {
    asm volatile(
        "mma.sync.aligned.m16n8k8.row.col.f32.tf32.tf32.f32 "
        "{%0,%1,%2,%3}, {%4,%5,%6,%7}, {%8,%9}, {%0,%1,%2,%3};\n"
        : "+f"(c[0]), "+f"(c[1]), "+f"(c[2]), "+f"(c[3])
        : "r"(a[0]), "r"(a[1]), "r"(a[2]), "r"(a[3]), "r"(b[0]), "r"(b[1]));
}

__device__ __forceinline__ float silu_f(float x) {
    return x / (1.0f + expf(-x));
}

// ---------------- kernels ----------------------------------------------------
__global__ void init_counts_kernel() {
    if (threadIdx.x < EM) g_count[threadIdx.x] = 0;
}

// One block per token: logits = x[t] @ Wr, softmax, top-2, bucket append.
__global__ void router_kernel(const float* __restrict__ x, const float* __restrict__ Wr) {
    const int t = blockIdx.x;
    const int tid = threadIdx.x;
    const float* xr = x + (size_t)t * DM;

    float acc[EM] = {0.f, 0.f, 0.f, 0.f};
    for (int d = tid; d < DM; d += 128) {
        const float xv = xr[d];
#pragma unroll
        for (int e = 0; e < EM; e++) acc[e] += xv * Wr[d * EM + e];
    }

    __shared__ float sred[EM][128];
#pragma unroll
    for (int e = 0; e < EM; e++) sred[e][tid] = acc[e];
    __syncthreads();
    for (int s = 64; s > 0; s >>= 1) {
        if (tid < s) {
#pragma unroll
            for (int e = 0; e < EM; e++) sred[e][tid] += sred[e][tid + s];
        }
        __syncthreads();
    }

    if (tid == 0) {
        float l[EM];
#pragma unroll
        for (int e = 0; e < EM; e++) l[e] = sred[e][0];
        float mx = l[0];
#pragma unroll
        for (int e = 1; e < EM; e++) mx = fmaxf(mx, l[e]);
        float p[EM], sum = 0.f;
#pragma unroll
        for (int e = 0; e < EM; e++) { p[e] = expf(l[e] - mx); sum += p[e]; }
        const float inv = 1.0f / sum;
#pragma unroll
        for (int e = 0; e < EM; e++) p[e] *= inv;

        // top-2, ties -> lower index (matches jax top_k)
        int e0 = 0;
#pragma unroll
        for (int e = 1; e < EM; e++) if (p[e] > p[e0]) e0 = e;
        int e1 = -1;
#pragma unroll
        for (int e = 0; e < EM; e++) {
            if (e == e0) continue;
            if (e1 < 0 || p[e] > p[e1]) e1 = e;
        }

        int s0 = atomicAdd(&g_count[e0], 1);
        g_bucket[e0 * T_TOK + s0] = t;
        g_gate[e0 * T_TOK + s0]   = p[e0];
        g_slot[t * KM + 0]        = e0 * T_TOK + s0;

        int s1 = atomicAdd(&g_count[e1], 1);
        g_bucket[e1 * T_TOK + s1] = t;
        g_gate[e1 * T_TOK + s1]   = p[e1];
        g_slot[t * KM + 1]        = e1 * T_TOK + s1;
    }
}

// Grouped GEMM1: for expert e, H[slot, f] = silu(x Wg) * (x Wu).
// grid = (m_tiles=16, f_tiles=128, experts=4), block = 256 threads.
__global__ __launch_bounds__(NTHREADS)
void gemm1_kernel(const float* __restrict__ x,
                  const float* __restrict__ Wg,
                  const float* __restrict__ Wu) {
    const int e  = blockIdx.z;
    const int cnt = g_count[e];
    const int m0 = blockIdx.x * BM;
    if (m0 >= cnt) return;
    const int f0 = blockIdx.y * BN;

    const int tid  = threadIdx.x;
    const int warp = tid >> 5;
    const int lane = tid & 31;
    const int wm = warp & 3;        // 4 warps along M (32 rows each)
    const int wn = warp >> 2;       // 2 warps along N (32 cols each)
    const int q  = lane >> 2;       // 0..7
    const int r2 = lane & 3;        // 0..3

    __shared__ __align__(16) uint32_t As[BM][36];
    __shared__ __align__(16) uint32_t Bg[BK][72];
    __shared__ __align__(16) uint32_t Bu[BK][72];
    __shared__ int rows[BM];

    if (tid < BM) {
        const int m = m0 + tid;
        rows[tid] = (m < cnt) ? g_bucket[e * T_TOK + m] : -1;
    }

    const float* Wge = Wg + (size_t)e * DM * FM;
    const float* Wue = Wu + (size_t)e * DM * FM;

    float accG[2][4][4];
    float accU[2][4][4];
#pragma unroll
    for (int mi = 0; mi < 2; mi++)
#pragma unroll
        for (int ni = 0; ni < 4; ni++)
#pragma unroll
            for (int j = 0; j < 4; j++) { accG[mi][ni][j] = 0.f; accU[mi][ni][j] = 0.f; }

    __syncthreads();

    for (int kt = 0; kt < DM / BK; kt++) {
        const int k0 = kt * BK;
        // A tile: 128 x 32 floats, gathered rows, tf32-converted
#pragma unroll
        for (int p = 0; p < 4; p++) {
            const int idx = tid + p * NTHREADS;
            const int rr = idx >> 3;
            const int c4 = idx & 7;
            const int tok = rows[rr];
            float4 v = make_float4(0.f, 0.f, 0.f, 0.f);
            if (tok >= 0)
                v = *(const float4*)(x + (size_t)tok * DM + k0 + c4 * 4);
            uint4 w = make_uint4(f2tf(v.x), f2tf(v.y), f2tf(v.z), f2tf(v.w));
            *(uint4*)&As[rr][c4 * 4] = w;
        }
        // B tiles: 32 x 64 each for Wg and Wu
#pragma unroll
        for (int p = 0; p < 2; p++) {
            const int idx = tid + p * NTHREADS;
            const int kr = idx >> 4;
            const int c4 = idx & 15;
            const size_t goff = (size_t)(k0 + kr) * FM + f0 + c4 * 4;
            float4 vg = *(const float4*)(Wge + goff);
            float4 vu = *(const float4*)(Wue + goff);
            *(uint4*)&Bg[kr][c4 * 4] = make_uint4(f2tf(vg.x), f2tf(vg.y), f2tf(vg.z), f2tf(vg.w));
            *(uint4*)&Bu[kr][c4 * 4] = make_uint4(f2tf(vu.x), f2tf(vu.y), f2tf(vu.z), f2tf(vu.w));
        }
        __syncthreads();

#pragma unroll
        for (int k8 = 0; k8 < 4; k8++) {
            const int kk = k8 * 8;
            uint32_t a[2][4];
#pragma unroll
            for (int mi = 0; mi < 2; mi++) {
                const int mr = wm * 32 + mi * 16 + q;
                a[mi][0] = As[mr][kk + r2];
                a[mi][1] = As[mr + 8][kk + r2];
                a[mi][2] = As[mr][kk + r2 + 4];
                a[mi][3] = As[mr + 8][kk + r2 + 4];
            }
#pragma unroll
            for (int ni = 0; ni < 4; ni++) {
                const int nc = wn * 32 + ni * 8 + q;
                uint32_t bg[2] = { Bg[kk + r2][nc], Bg[kk + r2 + 4][nc] };
                uint32_t bu[2] = { Bu[kk + r2][nc], Bu[kk + r2 + 4][nc] };
#pragma unroll
                for (int mi = 0; mi < 2; mi++) {
                    mma_tf32(accG[mi][ni], a[mi], bg);
                    mma_tf32(accU[mi][ni], a[mi], bu);
                }
            }
        }
        __syncthreads();
    }

    // Epilogue: H = silu(g)*u   (padded rows computed from zero A -> write 0, harmless)
#pragma unroll
    for (int mi = 0; mi < 2; mi++) {
#pragma unroll
        for (int ni = 0; ni < 4; ni++) {
            const int mloc = wm * 32 + mi * 16 + q;
            const int col  = f0 + wn * 32 + ni * 8 + r2 * 2;
            const int row0 = m0 + mloc;
            const int row1 = row0 + 8;
            float* h0 = g_H + ((size_t)(e * T_TOK) + row0) * FM + col;
            float* h1 = g_H + ((size_t)(e * T_TOK) + row1) * FM + col;
            h0[0] = silu_f(accG[mi][ni][0]) * accU[mi][ni][0];
            h0[1] = silu_f(accG[mi][ni][1]) * accU[mi][ni][1];
            h1[0] = silu_f(accG[mi][ni][2]) * accU[mi][ni][2];
            h1[1] = silu_f(accG[mi][ni][3]) * accU[mi][ni][3];
        }
    }
}

// Grouped GEMM2: Y[slot, d] = H[slot, :] @ Wd[e].
// grid = (m_tiles=16, d_tiles=32, experts=4), block = 256 threads.
__global__ __launch_bounds__(NTHREADS)
void gemm2_kernel(const float* __restrict__ Wd) {
    const int e  = blockIdx.z;
    const int cnt = g_count[e];
    const int m0 = blockIdx.x * BM;
    if (m0 >= cnt) return;
    const int d0 = blockIdx.y * BN;

    const int tid  = threadIdx.x;
    const int warp = tid >> 5;
    const int lane = tid & 31;
    const int wm = warp & 3;
    const int wn = warp >> 2;
    const int q  = lane >> 2;
    const int r2 = lane & 3;

    __shared__ __align__(16) uint32_t As[BM][36];
    __shared__ __align__(16) uint32_t Bs[BK][72];

    const float* Wde = Wd + (size_t)e * FM * DM;
    const float* Hbase = g_H + (size_t)(e * T_TOK + m0) * FM;

    float acc[2][4][4];
#pragma unroll
    for (int mi = 0; mi < 2; mi++)
#pragma unroll
        for (int ni = 0; ni < 4; ni++)
#pragma unroll
            for (int j = 0; j < 4; j++) acc[mi][ni][j] = 0.f;

    for (int kt = 0; kt < FM / BK; kt++) {
        const int k0 = kt * BK;
#pragma unroll
        for (int p = 0; p < 4; p++) {
            const int idx = tid + p * NTHREADS;
            const int rr = idx >> 3;
            const int c4 = idx & 7;
            float4 v = *(const float4*)(Hbase + (size_t)rr * FM + k0 + c4 * 4);
            *(uint4*)&As[rr][c4 * 4] = make_uint4(f2tf(v.x), f2tf(v.y), f2tf(v.z), f2tf(v.w));
        }
#pragma unroll
        for (int p = 0; p < 2; p++) {
            const int idx = tid + p * NTHREADS;
            const int kr = idx >> 4;
            const int c4 = idx & 15;
            float4 v = *(const float4*)(Wde + (size_t)(k0 + kr) * DM + d0 + c4 * 4);
            *(uint4*)&Bs[kr][c4 * 4] = make_uint4(f2tf(v.x), f2tf(v.y), f2tf(v.z), f2tf(v.w));
        }
        __syncthreads();

#pragma unroll
        for (int k8 = 0; k8 < 4; k8++) {
            const int kk = k8 * 8;
            uint32_t a[2][4];
#pragma unroll
            for (int mi = 0; mi < 2; mi++) {
                const int mr = wm * 32 + mi * 16 + q;
                a[mi][0] = As[mr][kk + r2];
                a[mi][1] = As[mr + 8][kk + r2];
                a[mi][2] = As[mr][kk + r2 + 4];
                a[mi][3] = As[mr + 8][kk + r2 + 4];
            }
#pragma unroll
            for (int ni = 0; ni < 4; ni++) {
                const int nc = wn * 32 + ni * 8 + q;
                uint32_t b[2] = { Bs[kk + r2][nc], Bs[kk + r2 + 4][nc] };
#pragma unroll
                for (int mi = 0; mi < 2; mi++) {
                    mma_tf32(acc[mi][ni], a[mi], b);
                }
            }
        }
        __syncthreads();
    }

#pragma unroll
    for (int mi = 0; mi < 2; mi++) {
#pragma unroll
        for (int ni = 0; ni < 4; ni++) {
            const int mloc = wm * 32 + mi * 16 + q;
            const int col  = d0 + wn * 32 + ni * 8 + r2 * 2;
            const int row0 = m0 + mloc;
            const int row1 = row0 + 8;
            float* y0 = g_Y + ((size_t)(e * T_TOK) + row0) * DM + col;
            float* y1 = g_Y + ((size_t)(e * T_TOK) + row1) * DM + col;
            y0[0] = acc[mi][ni][0];
            y0[1] = acc[mi][ni][1];
            y1[0] = acc[mi][ni][2];
            y1[1] = acc[mi][ni][3];
        }
    }
}

// out[t, :] = gate0 * Y[slot0, :] + gate1 * Y[slot1, :]
__global__ void combine_kernel(float* __restrict__ out) {
    const int i = blockIdx.x * blockDim.x + threadIdx.x;   // over T*DM/4 float4s
    const int t = i / (DM / 4);
    const int c = i % (DM / 4);
    const int s0 = g_slot[t * KM + 0];
    const int s1 = g_slot[t * KM + 1];
    const float w0 = g_gate[s0];
    const float w1 = g_gate[s1];
    const float4 y0 = *((const float4*)g_Y + (size_t)s0 * (DM / 4) + c);
    const float4 y1 = *((const float4*)g_Y + (size_t)s1 * (DM / 4) + c);
    float4 o;
    o.x = w0 * y0.x + w1 * y1.x;
    o.y = w0 * y0.y + w1 * y1.y;
    o.z = w0 * y0.z + w1 * y1.z;
    o.w = w0 * y0.w + w1 * y1.w;
    *((float4*)out + i) = o;
}

// ---------------- launch ------------------------------------------------------
extern "C" void kernel_launch(void* const* d_in, const int* in_sizes, int n_in,
                              void* d_out, int out_size) {
    const float* x  = (const float*)d_in[0];
    const float* Wr = (const float*)d_in[1];
    const float* Wg = (const float*)d_in[2];
    const float* Wu = (const float*)d_in[3];
    const float* Wd = (const float*)d_in[4];
    float* out = (float*)d_out;

    init_counts_kernel<<<1, 32>>>();
    router_kernel<<<T_TOK, 128>>>(x, Wr);
    gemm1_kernel<<<dim3(T_TOK / BM, FM / BN, EM), NTHREADS>>>(x, Wg, Wu);
    gemm2_kernel<<<dim3(T_TOK / BM, DM / BN, EM), NTHREADS>>>(Wd);
    combine_kernel<<<(T_TOK * DM / 4) / NTHREADS, NTHREADS>>>(out);
}

// round 4
// speedup vs baseline: 1.3723x; 1.3696x over previous
#include <cuda_runtime.h>
#include <cstdint>
#include <math.h>

#define T_TOK 2048
#define DM    2048
#define FM    8192
#define EM    4
#define KM    2

// ---------------- scratch ----------------------------------------------------
__device__ int   g_count[EM];
__device__ int   g_bucket[EM * T_TOK];
__device__ float g_gate[EM * T_TOK];
__device__ int   g_slot[T_TOK * KM];
__device__ float g_H[(size_t)EM * T_TOK * FM];   // SwiGLU hidden
__device__ float g_Y[(size_t)EM * T_TOK * DM];   // per-slot output

// ---------------- helpers ----------------------------------------------------
__device__ __forceinline__ uint32_t f2tf(float f) {
    uint32_t r; asm("cvt.rna.tf32.f32 %0, %1;" : "=r"(r) : "f"(f)); return r;
}

__device__ __forceinline__ void mma_tf32(float* c, const uint32_t* a, const uint32_t* b) {
    asm volatile(
        "mma.sync.aligned.m16n8k8.row.col.f32.tf32.tf32.f32 "
        "{%0,%1,%2,%3}, {%4,%5,%6,%7}, {%8,%9}, {%0,%1,%2,%3};\n"
        : "+f"(c[0]), "+f"(c[1]), "+f"(c[2]), "+f"(c[3])
        : "r"(a[0]), "r"(a[1]), "r"(a[2]), "r"(a[3]), "r"(b[0]), "r"(b[1]));
}

__device__ __forceinline__ float silu_f(float x) { return x / (1.0f + expf(-x)); }

__device__ __forceinline__ uint32_t smem_u32(const void* p) {
    uint32_t a;
    asm("{ .reg .u64 t; cvta.to.shared.u64 t, %1; cvt.u32.u64 %0, t; }" : "=r"(a) : "l"(p));
    return a;
}

__device__ __forceinline__ void cpa16(uint32_t dst, const void* src, uint32_t sz) {
    asm volatile("cp.async.cg.shared.global [%0], [%1], 16, %2;\n"
                 :: "r"(dst), "l"(src), "r"(sz));
}
#define CP_COMMIT() asm volatile("cp.async.commit_group;\n" ::: "memory")
#define CP_WAIT1()  asm volatile("cp.async.wait_group 1;\n" ::: "memory")

// ---------------- small kernels ----------------------------------------------
__global__ void init_counts_kernel() { if (threadIdx.x < EM) g_count[threadIdx.x] = 0; }

__global__ void router_kernel(const float* __restrict__ x, const float* __restrict__ Wr) {
    const int t = blockIdx.x, tid = threadIdx.x;
    const float* xr = x + (size_t)t * DM;
    float acc[EM] = {0.f, 0.f, 0.f, 0.f};
    for (int d = tid; d < DM; d += 128) {
        const float xv = xr[d];
#pragma unroll
        for (int e = 0; e < EM; e++) acc[e] += xv * Wr[d * EM + e];
    }
    __shared__ float sred[EM][128];
#pragma unroll
    for (int e = 0; e < EM; e++) sred[e][tid] = acc[e];
    __syncthreads();
    for (int s = 64; s > 0; s >>= 1) {
        if (tid < s) {
#pragma unroll
            for (int e = 0; e < EM; e++) sred[e][tid] += sred[e][tid + s];
        }
        __syncthreads();
    }
    if (tid == 0) {
        float l[EM];
#pragma unroll
        for (int e = 0; e < EM; e++) l[e] = sred[e][0];
        float mx = l[0];
#pragma unroll
        for (int e = 1; e < EM; e++) mx = fmaxf(mx, l[e]);
        float p[EM], sum = 0.f;
#pragma unroll
        for (int e = 0; e < EM; e++) { p[e] = expf(l[e] - mx); sum += p[e]; }
        const float inv = 1.0f / sum;
#pragma unroll
        for (int e = 0; e < EM; e++) p[e] *= inv;
        int e0 = 0;
#pragma unroll
        for (int e = 1; e < EM; e++) if (p[e] > p[e0]) e0 = e;
        int e1 = -1;
#pragma unroll
        for (int e = 0; e < EM; e++) {
            if (e == e0) continue;
            if (e1 < 0 || p[e] > p[e1]) e1 = e;
        }
        int s0 = atomicAdd(&g_count[e0], 1);
        g_bucket[e0 * T_TOK + s0] = t; g_gate[e0 * T_TOK + s0] = p[e0];
        g_slot[t * KM + 0] = e0 * T_TOK + s0;
        int s1 = atomicAdd(&g_count[e1], 1);
        g_bucket[e1 * T_TOK + s1] = t; g_gate[e1 * T_TOK + s1] = p[e1];
        g_slot[t * KM + 1] = e1 * T_TOK + s1;
    }
}

// =============== GEMM1: H = silu(x Wg) * (x Wu) ===============================
// Block 128M x 128N(dual), 8 warps: wm=warp&1 (2x64M), wn=warp>>1 (4x32N).
// Warp tile 64x32 dual -> 32 MMAs / 32 LDS per k8 (16 FLOP/B).
#define G1_AP 36          // A pitch, words (144B/row)
#define G1_BP 136         // B pitch, words (544B/row); 136%32==8 -> conflict-free
#define G1_AB (128 * G1_AP * 4)          // 18432
#define G1_BB (32 * G1_BP * 4)           // 17408
#define G1_STAGE (G1_AB + 2 * G1_BB)     // 53248
#define G1_ROWS  (2 * G1_STAGE)          // 106496
#define G1_SMEM  (G1_ROWS + 512)

__global__ __launch_bounds__(256, 1)
void gemm1_kernel(const float* __restrict__ x,
                  const float* __restrict__ Wg,
                  const float* __restrict__ Wu) {
    extern __shared__ char sm[];
    const int e   = blockIdx.z;
    const int cnt = g_count[e];
    const int m0  = blockIdx.x * 128;
    if (m0 >= cnt) return;
    const int f0  = blockIdx.y * 128;

    const int tid = threadIdx.x, warp = tid >> 5, lane = tid & 31;
    const int wm = warp & 1, wn = warp >> 1;
    const int q = lane >> 2, r2 = lane & 3;
    const uint32_t sb = smem_u32(sm);
    int* rows = (int*)(sm + G1_ROWS);

    if (tid < 128) {
        const int m = m0 + tid;
        rows[tid] = (m < cnt) ? g_bucket[e * T_TOK + m] : -1;
    }
    __syncthreads();

    const float* Wge = Wg + (size_t)e * DM * FM + f0;
    const float* Wue = Wu + (size_t)e * DM * FM + f0;

    auto load_tile = [&](int s, int kt) {
        const int k0 = kt * 32;
        const uint32_t ab = sb + s * G1_STAGE;
#pragma unroll
        for (int p = 0; p < 4; p++) {               // A: 128 rows x 32 f = 1024 chunks
            const int idx = tid + p * 256;
            const int rr = idx >> 3, c = idx & 7;
            const int tok = rows[rr];
            const float* src = (tok >= 0) ? (x + (size_t)tok * DM + k0 + c * 4) : x;
            cpa16(ab + rr * (G1_AP * 4) + c * 16, src, (tok >= 0) ? 16u : 0u);
        }
#pragma unroll
        for (int p = 0; p < 4; p++) {               // Bg: 32 rows(k) x 128 f
            const int idx = tid + p * 256;
            const int kr = idx >> 5, c = idx & 31;
            cpa16(ab + G1_AB + kr * (G1_BP * 4) + c * 16,
                  Wge + (size_t)(k0 + kr) * FM + c * 4, 16);
        }
#pragma unroll
        for (int p = 0; p < 4; p++) {               // Bu
            const int idx = tid + p * 256;
            const int kr = idx >> 5, c = idx & 31;
            cpa16(ab + G1_AB + G1_BB + kr * (G1_BP * 4) + c * 16,
                  Wue + (size_t)(k0 + kr) * FM + c * 4, 16);
        }
    };

    float accG[4][4][4], accU[4][4][4];
#pragma unroll
    for (int mi = 0; mi < 4; mi++)
#pragma unroll
        for (int ni = 0; ni < 4; ni++)
#pragma unroll
            for (int j = 0; j < 4; j++) { accG[mi][ni][j] = 0.f; accU[mi][ni][j] = 0.f; }

    const int KT = DM / 32;   // 64
    load_tile(0, 0); CP_COMMIT();

    for (int kt = 0; kt < KT; kt++) {
        __syncthreads();                       // protect buffer being refilled
        if (kt + 1 < KT) load_tile((kt + 1) & 1, kt + 1);
        CP_COMMIT();
        CP_WAIT1();
        __syncthreads();

        const float* As = (const float*)(sm + (kt & 1) * G1_STAGE);
        const float* Bg = As + 128 * G1_AP;
        const float* Bu = Bg + 32 * G1_BP;

#pragma unroll
        for (int k8 = 0; k8 < 4; k8++) {
            const int kk = k8 * 8;
            uint32_t a[4][4];
#pragma unroll
            for (int mi = 0; mi < 4; mi++) {
                const int mr = wm * 64 + mi * 16 + q;
                a[mi][0] = f2tf(As[mr * G1_AP + kk + r2]);
                a[mi][1] = f2tf(As[(mr + 8) * G1_AP + kk + r2]);
                a[mi][2] = f2tf(As[mr * G1_AP + kk + r2 + 4]);
                a[mi][3] = f2tf(As[(mr + 8) * G1_AP + kk + r2 + 4]);
            }
#pragma unroll
            for (int ni = 0; ni < 4; ni++) {
                const int nc = wn * 32 + ni * 8 + q;
                uint32_t bg[2] = { f2tf(Bg[(kk + r2) * G1_BP + nc]),
                                   f2tf(Bg[(kk + r2 + 4) * G1_BP + nc]) };
                uint32_t bu[2] = { f2tf(Bu[(kk + r2) * G1_BP + nc]),
                                   f2tf(Bu[(kk + r2 + 4) * G1_BP + nc]) };
#pragma unroll
                for (int mi = 0; mi < 4; mi++) {
                    mma_tf32(accG[mi][ni], a[mi], bg);
                    mma_tf32(accU[mi][ni], a[mi], bu);
                }
            }
        }
    }

    // epilogue: h = silu(g)*u, c0/c1 -> row q, c2/c3 -> row q+8, cols r2*2..+1
    const int rb = m0 + wm * 64;
#pragma unroll
    for (int mi = 0; mi < 4; mi++) {
        const int r0 = rb + mi * 16 + q;
#pragma unroll
        for (int ni = 0; ni < 4; ni++) {
            const int col = f0 + wn * 32 + ni * 8 + r2 * 2;
            float* p0 = g_H + ((size_t)(e * T_TOK) + r0) * FM + col;
            float* p1 = p0 + (size_t)8 * FM;
            float2 v0, v1;
            v0.x = silu_f(accG[mi][ni][0]) * accU[mi][ni][0];
            v0.y = silu_f(accG[mi][ni][1]) * accU[mi][ni][1];
            v1.x = silu_f(accG[mi][ni][2]) * accU[mi][ni][2];
            v1.y = silu_f(accG[mi][ni][3]) * accU[mi][ni][3];
            *(float2*)p0 = v0;
            *(float2*)p1 = v1;
        }
    }
}

// =============== GEMM2: Y = H Wd ==============================================
// Block 128M x 256N, 8 warps 2x4, warp tile 64x64 -> 32 MMAs / 32 LDS per k8.
#define G2_AP 36
#define G2_BP 264         // 264%32==8 -> conflict-free; 1056B/row
#define G2_AB (128 * G2_AP * 4)          // 18432
#define G2_BB (32 * G2_BP * 4)           // 33792
#define G2_STAGE (G2_AB + G2_BB)         // 52224
#define G2_SMEM  (2 * G2_STAGE)

__global__ __launch_bounds__(256, 1)
void gemm2_kernel(const float* __restrict__ Wd) {
    extern __shared__ char sm[];
    const int e   = blockIdx.z;
    const int cnt = g_count[e];
    const int m0  = blockIdx.x * 128;
    if (m0 >= cnt) return;
    const int d0  = blockIdx.y * 256;

    const int tid = threadIdx.x, warp = tid >> 5, lane = tid & 31;
    const int wm = warp & 1, wn = warp >> 1;
    const int q = lane >> 2, r2 = lane & 3;
    const uint32_t sb = smem_u32(sm);

    const float* Hb  = g_H + (size_t)(e * T_TOK + m0) * FM;
    const float* Wde = Wd + (size_t)e * FM * DM + d0;

    auto load_tile = [&](int s, int kt) {
        const int k0 = kt * 32;
        const uint32_t ab = sb + s * G2_STAGE;
#pragma unroll
        for (int p = 0; p < 4; p++) {               // A: 128 x 32
            const int idx = tid + p * 256;
            const int rr = idx >> 3, c = idx & 7;
            cpa16(ab + rr * (G2_AP * 4) + c * 16, Hb + (size_t)rr * FM + k0 + c * 4, 16);
        }
#pragma unroll
        for (int p = 0; p < 8; p++) {               // B: 32 x 256 = 2048 chunks
            const int idx = tid + p * 256;
            const int kr = idx >> 6, c = idx & 63;
            cpa16(ab + G2_AB + kr * (G2_BP * 4) + c * 16,
                  Wde + (size_t)(k0 + kr) * DM + c * 4, 16);
        }
    };

    float acc[4][8][4];
#pragma unroll
    for (int mi = 0; mi < 4; mi++)
#pragma unroll
        for (int ni = 0; ni < 8; ni++)
#pragma unroll
            for (int j = 0; j < 4; j++) acc[mi][ni][j] = 0.f;

    const int KT = FM / 32;   // 256
    load_tile(0, 0); CP_COMMIT();

    for (int kt = 0; kt < KT; kt++) {
        __syncthreads();
        if (kt + 1 < KT) load_tile((kt + 1) & 1, kt + 1);
        CP_COMMIT();
        CP_WAIT1();
        __syncthreads();

        const float* As = (const float*)(sm + (kt & 1) * G2_STAGE);
        const float* Bs = As + 128 * G2_AP;

#pragma unroll
        for (int k8 = 0; k8 < 4; k8++) {
            const int kk = k8 * 8;
            uint32_t a[4][4];
#pragma unroll
            for (int mi = 0; mi < 4; mi++) {
                const int mr = wm * 64 + mi * 16 + q;
                a[mi][0] = f2tf(As[mr * G2_AP + kk + r2]);
                a[mi][1] = f2tf(As[(mr + 8) * G2_AP + kk + r2]);
                a[mi][2] = f2tf(As[mr * G2_AP + kk + r2 + 4]);
                a[mi][3] = f2tf(As[(mr + 8) * G2_AP + kk + r2 + 4]);
            }
#pragma unroll
            for (int ni = 0; ni < 8; ni++) {
                const int nc = wn * 64 + ni * 8 + q;
                uint32_t b[2] = { f2tf(Bs[(kk + r2) * G2_BP + nc]),
                                  f2tf(Bs[(kk + r2 + 4) * G2_BP + nc]) };
#pragma unroll
                for (int mi = 0; mi < 4; mi++)
                    mma_tf32(acc[mi][ni], a[mi], b);
            }
        }
    }

    const int rb = m0 + wm * 64;
#pragma unroll
    for (int mi = 0; mi < 4; mi++) {
        const int r0 = rb + mi * 16 + q;
#pragma unroll
        for (int ni = 0; ni < 8; ni++) {
            const int col = d0 + wn * 64 + ni * 8 + r2 * 2;
            float* p0 = g_Y + ((size_t)(e * T_TOK) + r0) * DM + col;
            float* p1 = p0 + (size_t)8 * DM;
            float2 v0, v1;
            v0.x = acc[mi][ni][0]; v0.y = acc[mi][ni][1];
            v1.x = acc[mi][ni][2]; v1.y = acc[mi][ni][3];
            *(float2*)p0 = v0;
            *(float2*)p1 = v1;
        }
    }
}

__global__ void combine_kernel(float* __restrict__ out) {
    const int i = blockIdx.x * blockDim.x + threadIdx.x;
    const int t = i / (DM / 4), c = i % (DM / 4);
    const int s0 = g_slot[t * KM + 0], s1 = g_slot[t * KM + 1];
    const float w0 = g_gate[s0], w1 = g_gate[s1];
    const float4 y0 = *((const float4*)g_Y + (size_t)s0 * (DM / 4) + c);
    const float4 y1 = *((const float4*)g_Y + (size_t)s1 * (DM / 4) + c);
    float4 o;
    o.x = w0 * y0.x + w1 * y1.x; o.y = w0 * y0.y + w1 * y1.y;
    o.z = w0 * y0.z + w1 * y1.z; o.w = w0 * y0.w + w1 * y1.w;
    *((float4*)out + i) = o;
}

// ---------------- launch ------------------------------------------------------
extern "C" void kernel_launch(void* const* d_in, const int* in_sizes, int n_in,
                              void* d_out, int out_size) {
    const float* x  = (const float*)d_in[0];
    const float* Wr = (const float*)d_in[1];
    const float* Wg = (const float*)d_in[2];
    const float* Wu = (const float*)d_in[3];
    const float* Wd = (const float*)d_in[4];
    float* out = (float*)d_out;

    cudaFuncSetAttribute(gemm1_kernel, cudaFuncAttributeMaxDynamicSharedMemorySize, G1_SMEM);
    cudaFuncSetAttribute(gemm2_kernel, cudaFuncAttributeMaxDynamicSharedMemorySize, G2_SMEM);

    init_counts_kernel<<<1, 32>>>();
    router_kernel<<<T_TOK, 128>>>(x, Wr);
    gemm1_kernel<<<dim3(T_TOK / 128, FM / 128, EM), 256, G1_SMEM>>>(x, Wg, Wu);
    gemm2_kernel<<<dim3(T_TOK / 128, DM / 256, EM), 256, G2_SMEM>>>(Wd);
    combine_kernel<<<(T_TOK * DM / 4) / 256, 256>>>(out);
}

// round 5
// speedup vs baseline: 1.3876x; 1.0111x over previous
#include <cuda_runtime.h>
#include <cstdint>
#include <math.h>

#define T_TOK 2048
#define DM    2048
#define FM    8192
#define EM    4
#define KM    2

// ---------------- scratch ----------------------------------------------------
__device__ int   g_count[EM];
__device__ int   g_bucket[EM * T_TOK];
__device__ float g_gate[EM * T_TOK];
__device__ int   g_slot[T_TOK * KM];
__device__ float g_H[(size_t)EM * T_TOK * FM];   // SwiGLU hidden (tf32-rounded)
__device__ float g_Y[(size_t)EM * T_TOK * DM];   // per-slot output

// ---------------- helpers ----------------------------------------------------
__device__ __forceinline__ uint32_t f2tf(float f) {
    uint32_t r; asm("cvt.rna.tf32.f32 %0, %1;" : "=r"(r) : "f"(f)); return r;
}
__device__ __forceinline__ float rtf(float f) { return __uint_as_float(f2tf(f)); }

__device__ __forceinline__ void mma_tf32(float* c, const uint32_t* a, const uint32_t* b) {
    asm volatile(
        "mma.sync.aligned.m16n8k8.row.col.f32.tf32.tf32.f32 "
        "{%0,%1,%2,%3}, {%4,%5,%6,%7}, {%8,%9}, {%0,%1,%2,%3};\n"
        : "+f"(c[0]), "+f"(c[1]), "+f"(c[2]), "+f"(c[3])
        : "r"(a[0]), "r"(a[1]), "r"(a[2]), "r"(a[3]), "r"(b[0]), "r"(b[1]));
}

__device__ __forceinline__ float silu_f(float x) { return x / (1.0f + expf(-x)); }

__device__ __forceinline__ uint32_t smem_u32(const void* p) {
    uint32_t a;
    asm("{ .reg .u64 t; cvta.to.shared.u64 t, %1; cvt.u32.u64 %0, t; }" : "=r"(a) : "l"(p));
    return a;
}

__device__ __forceinline__ void cpa16(uint32_t dst, const void* src, uint32_t sz) {
    asm volatile("cp.async.cg.shared.global [%0], [%1], 16, %2;\n"
                 :: "r"(dst), "l"(src), "r"(sz));
}
#define CP_COMMIT() asm volatile("cp.async.commit_group;\n" ::: "memory")
#define CP_WAIT1()  asm volatile("cp.async.wait_group 1;\n" ::: "memory")

// ---------------- small kernels ----------------------------------------------
__global__ void init_counts_kernel() { if (threadIdx.x < EM) g_count[threadIdx.x] = 0; }

__global__ void router_kernel(const float* __restrict__ x, const float* __restrict__ Wr) {
    const int t = blockIdx.x, tid = threadIdx.x;
    const float* xr = x + (size_t)t * DM;
    float acc[EM] = {0.f, 0.f, 0.f, 0.f};
    for (int d = tid; d < DM; d += 128) {
        const float xv = xr[d];
#pragma unroll
        for (int e = 0; e < EM; e++) acc[e] += xv * Wr[d * EM + e];
    }
    __shared__ float sred[EM][128];
#pragma unroll
    for (int e = 0; e < EM; e++) sred[e][tid] = acc[e];
    __syncthreads();
    for (int s = 64; s > 0; s >>= 1) {
        if (tid < s) {
#pragma unroll
            for (int e = 0; e < EM; e++) sred[e][tid] += sred[e][tid + s];
        }
        __syncthreads();
    }
    if (tid == 0) {
        float l[EM];
#pragma unroll
        for (int e = 0; e < EM; e++) l[e] = sred[e][0];
        float mx = l[0];
#pragma unroll
        for (int e = 1; e < EM; e++) mx = fmaxf(mx, l[e]);
        float p[EM], sum = 0.f;
#pragma unroll
        for (int e = 0; e < EM; e++) { p[e] = expf(l[e] - mx); sum += p[e]; }
        const float inv = 1.0f / sum;
#pragma unroll
        for (int e = 0; e < EM; e++) p[e] *= inv;
        int e0 = 0;
#pragma unroll
        for (int e = 1; e < EM; e++) if (p[e] > p[e0]) e0 = e;
        int e1 = -1;
#pragma unroll
        for (int e = 0; e < EM; e++) {
            if (e == e0) continue;
            if (e1 < 0 || p[e] > p[e1]) e1 = e;
        }
        int s0 = atomicAdd(&g_count[e0], 1);
        g_bucket[e0 * T_TOK + s0] = t; g_gate[e0 * T_TOK + s0] = p[e0];
        g_slot[t * KM + 0] = e0 * T_TOK + s0;
        int s1 = atomicAdd(&g_count[e1], 1);
        g_bucket[e1 * T_TOK + s1] = t; g_gate[e1 * T_TOK + s1] = p[e1];
        g_slot[t * KM + 1] = e1 * T_TOK + s1;
    }
}

// =============== GEMM1: H = silu(x Wg) * (x Wu) ===============================
// Block 128M x 64F dual. 8 warps: wm=warp&3 (4x32M), wn=warp>>2 (2x32F).
// Warp tile 32x32 dual. 3-stage cp.async pipeline, ONE sync per k-iter.
#define G1_AP 36                       // A pitch (words)
#define G1_BP 72                       // B pitch (words), 72%32==8 -> conflict-free
#define G1_AB (128 * G1_AP * 4)        // 18432
#define G1_BB (32 * G1_BP * 4)         // 9216
#define G1_STAGE (G1_AB + 2 * G1_BB)   // 36864
#define G1_ROWS  (3 * G1_STAGE)        // 110592
#define G1_SMEM  (G1_ROWS + 512)

__global__ __launch_bounds__(256, 2)
void gemm1_kernel(const float* __restrict__ x,
                  const float* __restrict__ Wg,
                  const float* __restrict__ Wu) {
    extern __shared__ char sm[];
    const int e   = blockIdx.z;
    const int cnt = g_count[e];
    const int m0  = blockIdx.x * 128;
    if (m0 >= cnt) return;
    const int f0  = blockIdx.y * 64;

    const int tid = threadIdx.x, warp = tid >> 5, lane = tid & 31;
    const int wm = warp & 3, wn = warp >> 2;
    const int q = lane >> 2, r2 = lane & 3;
    const uint32_t sb = smem_u32(sm);
    int* rows = (int*)(sm + G1_ROWS);

    if (tid < 128) {
        const int m = m0 + tid;
        rows[tid] = (m < cnt) ? g_bucket[e * T_TOK + m] : -1;
    }
    __syncthreads();

    const float* Wge = Wg + (size_t)e * DM * FM + f0;
    const float* Wue = Wu + (size_t)e * DM * FM + f0;

    auto load_tile = [&](int s, int kt) {
        const int k0 = kt * 32;
        const uint32_t ab = sb + s * G1_STAGE;
#pragma unroll
        for (int p = 0; p < 4; p++) {               // A: 128x32 = 1024 16B-chunks
            const int idx = tid + p * 256;
            const int rr = idx >> 3, c = idx & 7;
            const int tok = rows[rr];
            const float* src = (tok >= 0) ? (x + (size_t)tok * DM + k0 + c * 4) : x;
            cpa16(ab + rr * (G1_AP * 4) + c * 16, src, (tok >= 0) ? 16u : 0u);
        }
        {                                            // Bg: 32x64 = 512 chunks (2/thread)
            const int kr = tid >> 4, c = tid & 15;
            cpa16(ab + G1_AB + kr * (G1_BP * 4) + c * 16,
                  Wge + (size_t)(k0 + kr) * FM + c * 4, 16);
            const int kr2 = kr + 16;
            cpa16(ab + G1_AB + kr2 * (G1_BP * 4) + c * 16,
                  Wge + (size_t)(k0 + kr2) * FM + c * 4, 16);
        }
        {                                            // Bu
            const int kr = tid >> 4, c = tid & 15;
            cpa16(ab + G1_AB + G1_BB + kr * (G1_BP * 4) + c * 16,
                  Wue + (size_t)(k0 + kr) * FM + c * 4, 16);
            const int kr2 = kr + 16;
            cpa16(ab + G1_AB + G1_BB + kr2 * (G1_BP * 4) + c * 16,
                  Wue + (size_t)(k0 + kr2) * FM + c * 4, 16);
        }
    };

    float accG[2][4][4], accU[2][4][4];
#pragma unroll
    for (int mi = 0; mi < 2; mi++)
#pragma unroll
        for (int ni = 0; ni < 4; ni++)
#pragma unroll
            for (int j = 0; j < 4; j++) { accG[mi][ni][j] = 0.f; accU[mi][ni][j] = 0.f; }

    const int KT = DM / 32;   // 64
    load_tile(0, 0); CP_COMMIT();
    load_tile(1, 1); CP_COMMIT();

    for (int kt = 0; kt < KT; kt++) {
        CP_WAIT1();
        __syncthreads();
        // safe: every warp passed the barrier => done reading stage (kt-1)%3
        if (kt + 2 < KT) load_tile((kt + 2) % 3, kt + 2);

        const float* As = (const float*)(sm + (kt % 3) * G1_STAGE);
        const float* Bg = As + 128 * G1_AP;
        const float* Bu = Bg + 32 * G1_BP;

#pragma unroll
        for (int k8 = 0; k8 < 4; k8++) {
            const int kk = k8 * 8;
            uint32_t a[2][4];
#pragma unroll
            for (int mi = 0; mi < 2; mi++) {
                const int mr = wm * 32 + mi * 16 + q;
                a[mi][0] = f2tf(As[mr * G1_AP + kk + r2]);
                a[mi][1] = f2tf(As[(mr + 8) * G1_AP + kk + r2]);
                a[mi][2] = f2tf(As[mr * G1_AP + kk + r2 + 4]);
                a[mi][3] = f2tf(As[(mr + 8) * G1_AP + kk + r2 + 4]);
            }
#pragma unroll
            for (int ni = 0; ni < 4; ni++) {
                const int nc = wn * 32 + ni * 8 + q;
                uint32_t bg[2] = { f2tf(Bg[(kk + r2) * G1_BP + nc]),
                                   f2tf(Bg[(kk + r2 + 4) * G1_BP + nc]) };
                uint32_t bu[2] = { f2tf(Bu[(kk + r2) * G1_BP + nc]),
                                   f2tf(Bu[(kk + r2 + 4) * G1_BP + nc]) };
#pragma unroll
                for (int mi = 0; mi < 2; mi++) {
                    mma_tf32(accG[mi][ni], a[mi], bg);
                    mma_tf32(accU[mi][ni], a[mi], bu);
                }
            }
        }
        CP_COMMIT();
    }

    // epilogue: H = rtf(silu(g)*u)  -> gemm2 can skip A-side cvt
    const int rb = m0 + wm * 32;
#pragma unroll
    for (int mi = 0; mi < 2; mi++) {
        const int r0 = rb + mi * 16 + q;
#pragma unroll
        for (int ni = 0; ni < 4; ni++) {
            const int col = f0 + wn * 32 + ni * 8 + r2 * 2;
            float* p0 = g_H + ((size_t)(e * T_TOK) + r0) * FM + col;
            float* p1 = p0 + (size_t)8 * FM;
            float2 v0, v1;
            v0.x = rtf(silu_f(accG[mi][ni][0]) * accU[mi][ni][0]);
            v0.y = rtf(silu_f(accG[mi][ni][1]) * accU[mi][ni][1]);
            v1.x = rtf(silu_f(accG[mi][ni][2]) * accU[mi][ni][2]);
            v1.y = rtf(silu_f(accG[mi][ni][3]) * accU[mi][ni][3]);
            *(float2*)p0 = v0;
            *(float2*)p1 = v1;
        }
    }
}

// =============== GEMM2: Y = H Wd ==============================================
// Block 128M x 128N. 8 warps: wm=warp&1 (2x64M), wn=warp>>1 (4x32N).
// Warp tile 64x32. A (H) is pre-rounded -> no cvt on A path.
#define G2_AP 36
#define G2_BP 136                       // 136%32==8 -> conflict-free
#define G2_AB (128 * G2_AP * 4)         // 18432
#define G2_BB (32 * G2_BP * 4)          // 17408
#define G2_STAGE (G2_AB + G2_BB)        // 35840
#define G2_SMEM  (3 * G2_STAGE)         // 107520

__global__ __launch_bounds__(256, 2)
void gemm2_kernel(const float* __restrict__ Wd) {
    extern __shared__ char sm[];
    const int e   = blockIdx.z;
    const int cnt = g_count[e];
    const int m0  = blockIdx.x * 128;
    if (m0 >= cnt) return;
    const int d0  = blockIdx.y * 128;

    const int tid = threadIdx.x, warp = tid >> 5, lane = tid & 31;
    const int wm = warp & 1, wn = warp >> 1;
    const int q = lane >> 2, r2 = lane & 3;
    const uint32_t sb = smem_u32(sm);

    const float* Hb  = g_H + (size_t)(e * T_TOK + m0) * FM;
    const float* Wde = Wd + (size_t)e * FM * DM + d0;

    auto load_tile = [&](int s, int kt) {
        const int k0 = kt * 32;
        const uint32_t ab = sb + s * G2_STAGE;
#pragma unroll
        for (int p = 0; p < 4; p++) {               // A: 128x32
            const int idx = tid + p * 256;
            const int rr = idx >> 3, c = idx & 7;
            cpa16(ab + rr * (G2_AP * 4) + c * 16, Hb + (size_t)rr * FM + k0 + c * 4, 16);
        }
#pragma unroll
        for (int p = 0; p < 4; p++) {               // B: 32x128 = 1024 chunks
            const int idx = tid + p * 256;
            const int kr = idx >> 5, c = idx & 31;
            cpa16(ab + G2_AB + kr * (G2_BP * 4) + c * 16,
                  Wde + (size_t)(k0 + kr) * DM + c * 4, 16);
        }
    };

    float acc[4][4][4];
#pragma unroll
    for (int mi = 0; mi < 4; mi++)
#pragma unroll
        for (int ni = 0; ni < 4; ni++)
#pragma unroll
            for (int j = 0; j < 4; j++) acc[mi][ni][j] = 0.f;

    const int KT = FM / 32;   // 256
    load_tile(0, 0); CP_COMMIT();
    load_tile(1, 1); CP_COMMIT();

    for (int kt = 0; kt < KT; kt++) {
        CP_WAIT1();
        __syncthreads();
        if (kt + 2 < KT) load_tile((kt + 2) % 3, kt + 2);

        const uint32_t* As = (const uint32_t*)(sm + (kt % 3) * G2_STAGE);
        const float*    Bs = (const float*)(As + 128 * G2_AP);

#pragma unroll
        for (int k8 = 0; k8 < 4; k8++) {
            const int kk = k8 * 8;
            uint32_t a[4][4];
#pragma unroll
            for (int mi = 0; mi < 4; mi++) {
                const int mr = wm * 64 + mi * 16 + q;
                a[mi][0] = As[mr * G2_AP + kk + r2];           // pre-rounded H: no cvt
                a[mi][1] = As[(mr + 8) * G2_AP + kk + r2];
                a[mi][2] = As[mr * G2_AP + kk + r2 + 4];
                a[mi][3] = As[(mr + 8) * G2_AP + kk + r2 + 4];
            }
#pragma unroll
            for (int ni = 0; ni < 4; ni++) {
                const int nc = wn * 32 + ni * 8 + q;
                uint32_t b[2] = { f2tf(Bs[(kk + r2) * G2_BP + nc]),
                                  f2tf(Bs[(kk + r2 + 4) * G2_BP + nc]) };
#pragma unroll
                for (int mi = 0; mi < 4; mi++)
                    mma_tf32(acc[mi][ni], a[mi], b);
            }
        }
        CP_COMMIT();
    }

    const int rb = m0 + wm * 64;
#pragma unroll
    for (int mi = 0; mi < 4; mi++) {
        const int r0 = rb + mi * 16 + q;
#pragma unroll
        for (int ni = 0; ni < 4; ni++) {
            const int col = d0 + wn * 32 + ni * 8 + r2 * 2;
            float* p0 = g_Y + ((size_t)(e * T_TOK) + r0) * DM + col;
            float* p1 = p0 + (size_t)8 * DM;
            float2 v0, v1;
            v0.x = acc[mi][ni][0]; v0.y = acc[mi][ni][1];
            v1.x = acc[mi][ni][2]; v1.y = acc[mi][ni][3];
            *(float2*)p0 = v0;
            *(float2*)p1 = v1;
        }
    }
}

__global__ void combine_kernel(float* __restrict__ out) {
    const int i = blockIdx.x * blockDim.x + threadIdx.x;
    const int t = i / (DM / 4), c = i % (DM / 4);
    const int s0 = g_slot[t * KM + 0], s1 = g_slot[t * KM + 1];
    const float w0 = g_gate[s0], w1 = g_gate[s1];
    const float4 y0 = *((const float4*)g_Y + (size_t)s0 * (DM / 4) + c);
    const float4 y1 = *((const float4*)g_Y + (size_t)s1 * (DM / 4) + c);
    float4 o;
    o.x = w0 * y0.x + w1 * y1.x; o.y = w0 * y0.y + w1 * y1.y;
    o.z = w0 * y0.z + w1 * y1.z; o.w = w0 * y0.w + w1 * y1.w;
    *((float4*)out + i) = o;
}

// ---------------- launch ------------------------------------------------------
extern "C" void kernel_launch(void* const* d_in, const int* in_sizes, int n_in,
                              void* d_out, int out_size) {
    const float* x  = (const float*)d_in[0];
    const float* Wr = (const float*)d_in[1];
    const float* Wg = (const float*)d_in[2];
    const float* Wu = (const float*)d_in[3];
    const float* Wd = (const float*)d_in[4];
    float* out = (float*)d_out;

    cudaFuncSetAttribute(gemm1_kernel, cudaFuncAttributeMaxDynamicSharedMemorySize, G1_SMEM);
    cudaFuncSetAttribute(gemm2_kernel, cudaFuncAttributeMaxDynamicSharedMemorySize, G2_SMEM);

    init_counts_kernel<<<1, 32>>>();
    router_kernel<<<T_TOK, 128>>>(x, Wr);
    gemm1_kernel<<<dim3(T_TOK / 128, FM / 64, EM), 256, G1_SMEM>>>(x, Wg, Wu);
    gemm2_kernel<<<dim3(T_TOK / 128, DM / 128, EM), 256, G2_SMEM>>>(Wd);
    combine_kernel<<<(T_TOK * DM / 4) / 256, 256>>>(out);
}